// round 1
// baseline (speedup 1.0000x reference)
#include <cuda_runtime.h>

// Problem constants (fixed by setup_inputs: P=64, K=8, C=512, N=3*P*K=1536)
#define NROWS 1536
#define CDIM  512
#define MROWS 192      // 3*P
#define KINST 8        // NROWS / MROWS
#define KK    1024     // 2*CDIM  (packed [logx | xs] / [hcen | logh])
#define LOG_EPS -20.72326583694641f  // log(1e-9)
#define MARGIN 6.0f

// Scratch (device globals; no allocations allowed)
__device__ float g_A[NROWS * KK];      // [logx | xs]   6 MB
__device__ float g_B[MROWS * KK];      // [hcen | logh] 768 KB
__device__ float g_entx[NROWS];
__device__ float g_enth[MROWS];
__device__ int   g_pidi[NROWS];
__device__ int   g_pidhc[MROWS];
__device__ float g_acc[4];             // s1, s2, pos_cnt, neg_cnt

// ---------------------------------------------------------------------------
// Kernel 0: zero accumulators, detect pids element width (int32 vs int64),
// extract per-row pid and per-cluster pid.
// int64 little-endian with values in [0,64): every odd 32-bit word is 0.
// int32: pids[9]==1 etc. appear at odd word indices -> nonzero.
// ---------------------------------------------------------------------------
__global__ void prep_kernel(const int* __restrict__ pw) {
    int tid = threadIdx.x;
    if (tid < 4) g_acc[tid] = 0.0f;
    int q = 1 + 2 * tid;               // odd words 1..511 (safe for both widths)
    int nz = (pw[q] != 0) ? 1 : 0;
    int any = __syncthreads_or(nz);
    int stride = any ? 1 : 2;
    for (int i = tid; i < NROWS; i += blockDim.x) g_pidi[i]  = pw[i * stride];
    for (int j = tid; j < MROWS; j += blockDim.x) g_pidhc[j] = pw[j * KINST * stride];
}

// ---------------------------------------------------------------------------
// Kernel 1: row softmax -> write logx (clipped) and xs into packed A, ent_x.
// One warp per row, 16 elems per lane.
// ---------------------------------------------------------------------------
__global__ __launch_bounds__(256) void softmax_kernel(const float* __restrict__ x) {
    int warp = threadIdx.x >> 5;
    int lane = threadIdx.x & 31;
    int row = blockIdx.x * 8 + warp;
    if (row >= NROWS) return;
    const float* xr = x + (size_t)row * CDIM;
    float v[16];
    float mx = -1e30f;
#pragma unroll
    for (int t = 0; t < 16; t++) {
        v[t] = xr[t * 32 + lane];
        mx = fmaxf(mx, v[t]);
    }
#pragma unroll
    for (int o = 16; o > 0; o >>= 1) mx = fmaxf(mx, __shfl_xor_sync(0xffffffffu, mx, o));
    float e[16];
    float s = 0.f;
#pragma unroll
    for (int t = 0; t < 16; t++) { e[t] = __expf(v[t] - mx); s += e[t]; }
#pragma unroll
    for (int o = 16; o > 0; o >>= 1) s += __shfl_xor_sync(0xffffffffu, s, o);
    float ls = __logf(s);
    float inv = 1.0f / s;
    float ent = 0.f;
    float* Ar = g_A + (size_t)row * KK;
#pragma unroll
    for (int t = 0; t < 16; t++) {
        float lx = fmaxf(v[t] - mx - ls, LOG_EPS);   // log(clip(xs, eps))
        float xs = e[t] * inv;
        Ar[t * 32 + lane]        = lx;
        Ar[CDIM + t * 32 + lane] = xs;
        ent += xs * lx;
    }
#pragma unroll
    for (int o = 16; o > 0; o >>= 1) ent += __shfl_xor_sync(0xffffffffu, ent, o);
    if (lane == 0) g_entx[row] = ent;
}

// ---------------------------------------------------------------------------
// Kernel 2: cluster centers (mean of KINST rows of xs), logh, ent_h.
// One block per cluster j.
// ---------------------------------------------------------------------------
__global__ __launch_bounds__(256) void center_kernel() {
    int j = blockIdx.x;
    int tid = threadIdx.x;
    __shared__ float sred[256];
    float entp = 0.f;
    float* Bj = g_B + (size_t)j * KK;
    for (int c = tid; c < CDIM; c += 256) {
        float s = 0.f;
#pragma unroll
        for (int r = 0; r < KINST; r++)
            s += g_A[(size_t)(j * KINST + r) * KK + CDIM + c];
        float h = s * (1.0f / KINST);
        float lh = __logf(fmaxf(h, 1e-9f));
        Bj[c] = h;
        Bj[CDIM + c] = lh;
        entp += h * lh;
    }
    sred[tid] = entp;
    __syncthreads();
    for (int o = 128; o > 0; o >>= 1) {
        if (tid < o) sred[tid] += sred[tid + o];
        __syncthreads();
    }
    if (tid == 0) g_enth[j] = sred[0];
}

// ---------------------------------------------------------------------------
// Kernel 3: fused GEMM (A[1536x1024] x B[192x1024]^T) + masked loss reduction.
// BM=32, BN=64, BK=32, 128 threads, 4x4 thread tiles, double-buffered smem.
// Grid (48, 3) = 144 blocks ~ one full wave.
// ---------------------------------------------------------------------------
#define BM 32
#define BN 64
#define BK 32
#define PADA 4
#define PADB 4

__global__ __launch_bounds__(128) void gemm_loss_kernel() {
    __shared__ float As[2][BK][BM + PADA];
    __shared__ float Bs[2][BK][BN + PADB];
    int tid = threadIdx.x;
    int tx = tid & 15, ty = tid >> 4;          // 16 x 8 compute layout
    int i0 = blockIdx.x * BM;
    int j0 = blockIdx.y * BN;
    int lr = tid >> 3;                          // loader row 0..15
    int lc = (tid & 7) * 4;                     // loader k-col (float4)

    const float* Ag = g_A + (size_t)i0 * KK;
    const float* Bg = g_B + (size_t)j0 * KK;

    float acc[4][4] = {};

    // preload tile 0
    {
        float4 a0 = *(const float4*)(Ag + (size_t)lr * KK + lc);
        float4 a1 = *(const float4*)(Ag + (size_t)(lr + 16) * KK + lc);
        float4 b0 = *(const float4*)(Bg + (size_t)lr * KK + lc);
        float4 b1 = *(const float4*)(Bg + (size_t)(lr + 16) * KK + lc);
        float4 b2 = *(const float4*)(Bg + (size_t)(lr + 32) * KK + lc);
        float4 b3 = *(const float4*)(Bg + (size_t)(lr + 48) * KK + lc);
#pragma unroll
        for (int u = 0; u < 4; u++) {
            As[0][lc + u][lr]      = ((const float*)&a0)[u];
            As[0][lc + u][lr + 16] = ((const float*)&a1)[u];
            Bs[0][lc + u][lr]      = ((const float*)&b0)[u];
            Bs[0][lc + u][lr + 16] = ((const float*)&b1)[u];
            Bs[0][lc + u][lr + 32] = ((const float*)&b2)[u];
            Bs[0][lc + u][lr + 48] = ((const float*)&b3)[u];
        }
    }
    __syncthreads();

    const int NKT = KK / BK;  // 32
    for (int kt = 0; kt < NKT; kt++) {
        int b = kt & 1;
        float4 pa0, pa1, pb0, pb1, pb2, pb3;
        if (kt + 1 < NKT) {
            int ko = (kt + 1) * BK + lc;
            pa0 = *(const float4*)(Ag + (size_t)lr * KK + ko);
            pa1 = *(const float4*)(Ag + (size_t)(lr + 16) * KK + ko);
            pb0 = *(const float4*)(Bg + (size_t)lr * KK + ko);
            pb1 = *(const float4*)(Bg + (size_t)(lr + 16) * KK + ko);
            pb2 = *(const float4*)(Bg + (size_t)(lr + 32) * KK + ko);
            pb3 = *(const float4*)(Bg + (size_t)(lr + 48) * KK + ko);
        }
#pragma unroll
        for (int k = 0; k < BK; k++) {
            float4 av = *(const float4*)&As[b][k][ty * 4];
            float4 bv = *(const float4*)&Bs[b][k][tx * 4];
            float af[4] = {av.x, av.y, av.z, av.w};
            float bf[4] = {bv.x, bv.y, bv.z, bv.w};
#pragma unroll
            for (int r = 0; r < 4; r++)
#pragma unroll
                for (int t = 0; t < 4; t++)
                    acc[r][t] += af[r] * bf[t];
        }
        if (kt + 1 < NKT) {
            __syncthreads();
            int nb = 1 - b;
#pragma unroll
            for (int u = 0; u < 4; u++) {
                As[nb][lc + u][lr]      = ((const float*)&pa0)[u];
                As[nb][lc + u][lr + 16] = ((const float*)&pa1)[u];
                Bs[nb][lc + u][lr]      = ((const float*)&pb0)[u];
                Bs[nb][lc + u][lr + 16] = ((const float*)&pb1)[u];
                Bs[nb][lc + u][lr + 32] = ((const float*)&pb2)[u];
                Bs[nb][lc + u][lr + 48] = ((const float*)&pb3)[u];
            }
            __syncthreads();
        }
    }

    // Epilogue: dist -> masked loss contributions
    const int mid_n = 2 * NROWS / 3;  // 1024
    const int mid_m = 2 * MROWS / 3;  // 128
    float s1 = 0.f, s2 = 0.f, c1 = 0.f, c2 = 0.f;
    int ibase = i0 + ty * 4, jbase = j0 + tx * 4;
    float eh[4]; int ph[4]; bool jl[4];
#pragma unroll
    for (int t = 0; t < 4; t++) {
        int j = jbase + t;
        eh[t] = g_enth[j];
        ph[t] = g_pidhc[j];
        jl[t] = (j < mid_m);
    }
#pragma unroll
    for (int r = 0; r < 4; r++) {
        int i = ibase + r;
        float ex = g_entx[i];
        int pi = g_pidi[i];
        bool il = (i < mid_n);
#pragma unroll
        for (int t = 0; t < 4; t++) {
            float d = ex + eh[t] - acc[r][t];
            if (pi == ph[t]) {
                if (il != jl[t]) { s1 += d; c1 += 1.f; }   // cross-modality positive
            } else {
                s2 += fmaxf(MARGIN - d, 0.f);
                c2 += 1.f;
            }
        }
    }
#pragma unroll
    for (int o = 16; o > 0; o >>= 1) {
        s1 += __shfl_xor_sync(0xffffffffu, s1, o);
        s2 += __shfl_xor_sync(0xffffffffu, s2, o);
        c1 += __shfl_xor_sync(0xffffffffu, c1, o);
        c2 += __shfl_xor_sync(0xffffffffu, c2, o);
    }
    __shared__ float wred[4][4];
    int wp = tid >> 5, ln = tid & 31;
    if (ln == 0) { wred[wp][0] = s1; wred[wp][1] = s2; wred[wp][2] = c1; wred[wp][3] = c2; }
    __syncthreads();
    if (tid < 4) {
        float v = wred[0][tid] + wred[1][tid] + wred[2][tid] + wred[3][tid];
        atomicAdd(&g_acc[tid], v);
    }
}

// ---------------------------------------------------------------------------
// Kernel 4: finalize scalar loss
// ---------------------------------------------------------------------------
__global__ void finalize_kernel(float* __restrict__ out) {
    out[0] = g_acc[0] / fmaxf(g_acc[2], 1.f) + g_acc[1] / fmaxf(g_acc[3], 1.f);
}

extern "C" void kernel_launch(void* const* d_in, const int* in_sizes, int n_in,
                              void* d_out, int out_size) {
    const float* x = (const float*)d_in[0];
    const int* pids_words = (const int*)d_in[1];   // width auto-detected on device
    (void)in_sizes; (void)n_in; (void)out_size;

    prep_kernel<<<1, 256>>>(pids_words);
    softmax_kernel<<<NROWS / 8, 256>>>(x);
    center_kernel<<<MROWS, 256>>>();
    dim3 grid(NROWS / BM, MROWS / BN);             // (48, 3)
    gemm_loss_kernel<<<grid, 128>>>();
    finalize_kernel<<<1, 1>>>((float*)d_out);
}

// round 3
// speedup vs baseline: 1.7471x; 1.7471x over previous
#include <cuda_runtime.h>
#include <cstdint>

// Problem constants (fixed by setup_inputs: P=64, K=8, C=512, N=3*P*K=1536)
#define NROWS 1536
#define CDIM  512
#define MROWS 192      // 3*P
#define KINST 8        // NROWS / MROWS
#define KK    1024     // 2*CDIM  (packed [logx | xs] / [hcen | logh])
#define LOG_EPS -20.72326583694641f  // log(1e-9)
#define MARGIN 6.0f

// GEMM tiling (tf32 mma.sync m16n8k8)
#define KSPLIT 4
#define KCHUNK (KK / KSPLIT)   // 256 k per block
#define GBM 64
#define GBN 64
#define GBK 16                 // k per smem stage (2 k8 sub-steps)
#define NSTG (KCHUNK / GBK)    // 16
#define SPAD 4
#define SSTRIDE (GBK + SPAD)   // 20 words; 20 mod 32 = 20, 20%4=0 -> f4-aligned,
                               // frag LDS banks (20*(lane>>2)+(lane&3)) all distinct

// Scratch (device globals; no allocations allowed)
__device__ float g_A[NROWS * KK];            // [logx | xs]  (tf32-rounded)
__device__ float g_B[MROWS * KK];            // [hcen | logh] (tf32-rounded)
__device__ float g_C[KSPLIT][NROWS * MROWS]; // split-K partial dot products
__device__ float g_entx[NROWS];
__device__ float g_enth[MROWS];
__device__ int   g_pidi[NROWS];
__device__ int   g_pidhc[MROWS];
__device__ float g_acc[4];                   // s1, s2, pos_cnt, neg_cnt

__device__ __forceinline__ float to_tf32(float x) {
    uint32_t r;
    asm("cvt.rna.tf32.f32 %0, %1;" : "=r"(r) : "f"(x));
    return __uint_as_float(r);
}

// ---------------------------------------------------------------------------
// Kernel 0: zero accumulators, detect pids element width (int32 vs int64),
// extract per-row pid and per-cluster pid.
// ---------------------------------------------------------------------------
__global__ void prep_kernel(const int* __restrict__ pw) {
    int tid = threadIdx.x;
    if (tid < 4) g_acc[tid] = 0.0f;
    int q = 1 + 2 * tid;               // odd words 1..511 (safe for both widths)
    int nz = (pw[q] != 0) ? 1 : 0;
    int any = __syncthreads_or(nz);
    int stride = any ? 1 : 2;
    for (int i = tid; i < NROWS; i += blockDim.x) g_pidi[i]  = pw[i * stride];
    for (int j = tid; j < MROWS; j += blockDim.x) g_pidhc[j] = pw[j * KINST * stride];
}

// ---------------------------------------------------------------------------
// Kernel 1: row softmax -> logx (clipped) and xs into packed A (tf32), ent_x.
// ---------------------------------------------------------------------------
__global__ __launch_bounds__(256) void softmax_kernel(const float* __restrict__ x) {
    int warp = threadIdx.x >> 5;
    int lane = threadIdx.x & 31;
    int row = blockIdx.x * 8 + warp;
    const float* xr = x + (size_t)row * CDIM;
    float v[16];
    float mx = -1e30f;
#pragma unroll
    for (int t = 0; t < 16; t++) {
        v[t] = xr[t * 32 + lane];
        mx = fmaxf(mx, v[t]);
    }
#pragma unroll
    for (int o = 16; o > 0; o >>= 1) mx = fmaxf(mx, __shfl_xor_sync(0xffffffffu, mx, o));
    float e[16];
    float s = 0.f;
#pragma unroll
    for (int t = 0; t < 16; t++) { e[t] = __expf(v[t] - mx); s += e[t]; }
#pragma unroll
    for (int o = 16; o > 0; o >>= 1) s += __shfl_xor_sync(0xffffffffu, s, o);
    float ls = __logf(s);
    float inv = 1.0f / s;
    float ent = 0.f;
    float* Ar = g_A + (size_t)row * KK;
#pragma unroll
    for (int t = 0; t < 16; t++) {
        float lx = fmaxf(v[t] - mx - ls, LOG_EPS);
        float xs = e[t] * inv;
        Ar[t * 32 + lane]        = to_tf32(lx);
        Ar[CDIM + t * 32 + lane] = to_tf32(xs);
        ent += xs * lx;
    }
#pragma unroll
    for (int o = 16; o > 0; o >>= 1) ent += __shfl_xor_sync(0xffffffffu, ent, o);
    if (lane == 0) g_entx[row] = ent;
}

// ---------------------------------------------------------------------------
// Kernel 2: cluster centers (mean of KINST rows of xs), logh, ent_h.
// ---------------------------------------------------------------------------
__global__ __launch_bounds__(256) void center_kernel() {
    int j = blockIdx.x;
    int tid = threadIdx.x;
    __shared__ float sred[256];
    float entp = 0.f;
    float* Bj = g_B + (size_t)j * KK;
    for (int c = tid; c < CDIM; c += 256) {
        float s = 0.f;
#pragma unroll
        for (int r = 0; r < KINST; r++)
            s += g_A[(size_t)(j * KINST + r) * KK + CDIM + c];
        float h = s * (1.0f / KINST);
        float lh = __logf(fmaxf(h, 1e-9f));
        Bj[c]        = to_tf32(h);
        Bj[CDIM + c] = to_tf32(lh);
        entp += h * lh;
    }
    sred[tid] = entp;
    __syncthreads();
    for (int o = 128; o > 0; o >>= 1) {
        if (tid < o) sred[tid] += sred[tid + o];
        __syncthreads();
    }
    if (tid == 0) g_enth[j] = sred[0];
}

// ---------------------------------------------------------------------------
// Kernel 3: tf32 tensor-core GEMM, split-K, partials to g_C[z].
// 128 threads = 4 warps (2x2), warp tile 32x32 = 2x4 m16n8k8 mma tiles.
// Smem: plain row-major padded tiles [64][20]; all fragment loads are
// scalar LDS.32, conflict-free (bank = 20*(lane>>2)+(lane&3), all distinct).
// ---------------------------------------------------------------------------
__global__ __launch_bounds__(128) void mma_kernel() {
    __shared__ float As[2][GBM][SSTRIDE];
    __shared__ float Bs[2][GBN][SSTRIDE];
    const int tid = threadIdx.x;
    const int lane = tid & 31;
    const int wid = tid >> 5;
    const int wm = wid & 1, wn = wid >> 1;
    const int i0 = blockIdx.x * GBM;
    const int j0 = blockIdx.y * GBN;
    const float* Ag = g_A + (size_t)i0 * KK + blockIdx.z * KCHUNK;
    const float* Bg = g_B + (size_t)j0 * KK + blockIdx.z * KCHUNK;

    // Loaders: per stage, A = 64x16 = 256 float4, B same; 2 of each per thread.
    const int lrow0 = tid >> 2;             // 0..31
    const int lrow1 = lrow0 + 32;           // 32..63
    const int lkc   = (tid & 3) * 4;        // 0,4,8,12

    float c[2][4][4] = {};
    float4 va0, va1, vb0, vb1;

    // preload + store stage 0
    va0 = *(const float4*)(Ag + (size_t)lrow0 * KK + lkc);
    va1 = *(const float4*)(Ag + (size_t)lrow1 * KK + lkc);
    vb0 = *(const float4*)(Bg + (size_t)lrow0 * KK + lkc);
    vb1 = *(const float4*)(Bg + (size_t)lrow1 * KK + lkc);
    *(float4*)&As[0][lrow0][lkc] = va0;
    *(float4*)&As[0][lrow1][lkc] = va1;
    *(float4*)&Bs[0][lrow0][lkc] = vb0;
    *(float4*)&Bs[0][lrow1][lkc] = vb1;
    __syncthreads();

    const int fr = lane >> 2;   // 0..7 fragment row/col
    const int fk = lane & 3;    // 0..3 fragment k

    for (int st = 0; st < NSTG; st++) {
        const int buf = st & 1;
        if (st + 1 < NSTG) {
            int ck = (st + 1) * GBK;
            va0 = *(const float4*)(Ag + (size_t)lrow0 * KK + lkc + ck);
            va1 = *(const float4*)(Ag + (size_t)lrow1 * KK + lkc + ck);
            vb0 = *(const float4*)(Bg + (size_t)lrow0 * KK + lkc + ck);
            vb1 = *(const float4*)(Bg + (size_t)lrow1 * KK + lkc + ck);
        }
#pragma unroll
        for (int ks = 0; ks < 2; ks++) {
            const int k0 = ks * 8 + fk;
            uint32_t a[2][4], b[4][2];
#pragma unroll
            for (int mi = 0; mi < 2; mi++) {
                int r0 = wm * 32 + mi * 16 + fr;
                a[mi][0] = __float_as_uint(As[buf][r0][k0]);
                a[mi][1] = __float_as_uint(As[buf][r0 + 8][k0]);
                a[mi][2] = __float_as_uint(As[buf][r0][k0 + 4]);
                a[mi][3] = __float_as_uint(As[buf][r0 + 8][k0 + 4]);
            }
#pragma unroll
            for (int ni = 0; ni < 4; ni++) {
                int c0 = wn * 32 + ni * 8 + fr;
                b[ni][0] = __float_as_uint(Bs[buf][c0][k0]);
                b[ni][1] = __float_as_uint(Bs[buf][c0][k0 + 4]);
            }
#pragma unroll
            for (int mi = 0; mi < 2; mi++)
#pragma unroll
                for (int ni = 0; ni < 4; ni++)
                    asm volatile(
                        "mma.sync.aligned.m16n8k8.row.col.f32.tf32.tf32.f32 "
                        "{%0,%1,%2,%3}, {%4,%5,%6,%7}, {%8,%9}, {%0,%1,%2,%3};\n"
                        : "+f"(c[mi][ni][0]), "+f"(c[mi][ni][1]),
                          "+f"(c[mi][ni][2]), "+f"(c[mi][ni][3])
                        : "r"(a[mi][0]), "r"(a[mi][1]), "r"(a[mi][2]), "r"(a[mi][3]),
                          "r"(b[ni][0]), "r"(b[ni][1]));
        }
        if (st + 1 < NSTG) {
            __syncthreads();
            const int nb = buf ^ 1;
            *(float4*)&As[nb][lrow0][lkc] = va0;
            *(float4*)&As[nb][lrow1][lkc] = va1;
            *(float4*)&Bs[nb][lrow0][lkc] = vb0;
            *(float4*)&Bs[nb][lrow1][lkc] = vb1;
            __syncthreads();
        }
    }

    // Epilogue: write C partials (c0,c1 at (row, 2*fk), c2,c3 at row+8)
    float* Cz = g_C[blockIdx.z];
#pragma unroll
    for (int mi = 0; mi < 2; mi++) {
        int ib = i0 + wm * 32 + mi * 16 + fr;
#pragma unroll
        for (int ni = 0; ni < 4; ni++) {
            int jj = j0 + wn * 32 + ni * 8 + fk * 2;
            *(float2*)&Cz[(size_t)ib * MROWS + jj]       = make_float2(c[mi][ni][0], c[mi][ni][1]);
            *(float2*)&Cz[(size_t)(ib + 8) * MROWS + jj] = make_float2(c[mi][ni][2], c[mi][ni][3]);
        }
    }
}

// ---------------------------------------------------------------------------
// Kernel 4: reduce split-K partials -> dist -> masked loss accumulators.
// ---------------------------------------------------------------------------
__global__ __launch_bounds__(192) void reduce_kernel() {
    const int j = threadIdx.x;
    const float eh = g_enth[j];
    const int ph = g_pidhc[j];
    const bool jl = j < (2 * MROWS / 3);   // 128
    float s1 = 0.f, s2 = 0.f, c1 = 0.f, c2 = 0.f;
    const int i0 = blockIdx.x * 8;
#pragma unroll
    for (int u = 0; u < 8; u++) {
        int i = i0 + u;
        size_t e = (size_t)i * MROWS + j;
        float v = g_C[0][e] + g_C[1][e] + g_C[2][e] + g_C[3][e];
        float d = g_entx[i] + eh - v;
        bool il = i < (2 * NROWS / 3);     // 1024
        if (g_pidi[i] == ph) {
            if (il != jl) { s1 += d; c1 += 1.f; }
        } else {
            s2 += fmaxf(MARGIN - d, 0.f);
            c2 += 1.f;
        }
    }
#pragma unroll
    for (int o = 16; o > 0; o >>= 1) {
        s1 += __shfl_xor_sync(0xffffffffu, s1, o);
        s2 += __shfl_xor_sync(0xffffffffu, s2, o);
        c1 += __shfl_xor_sync(0xffffffffu, c1, o);
        c2 += __shfl_xor_sync(0xffffffffu, c2, o);
    }
    __shared__ float red[6][4];
    int w = j >> 5, ln = j & 31;
    if (ln == 0) { red[w][0] = s1; red[w][1] = s2; red[w][2] = c1; red[w][3] = c2; }
    __syncthreads();
    if (j < 4) {
        float v = 0.f;
#pragma unroll
        for (int w2 = 0; w2 < 6; w2++) v += red[w2][j];
        atomicAdd(&g_acc[j], v);
    }
}

// ---------------------------------------------------------------------------
// Kernel 5: finalize scalar loss
// ---------------------------------------------------------------------------
__global__ void finalize_kernel(float* __restrict__ out) {
    out[0] = g_acc[0] / fmaxf(g_acc[2], 1.f) + g_acc[1] / fmaxf(g_acc[3], 1.f);
}

extern "C" void kernel_launch(void* const* d_in, const int* in_sizes, int n_in,
                              void* d_out, int out_size) {
    const float* x = (const float*)d_in[0];
    const int* pids_words = (const int*)d_in[1];   // width auto-detected on device
    (void)in_sizes; (void)n_in; (void)out_size;

    prep_kernel<<<1, 256>>>(pids_words);
    softmax_kernel<<<NROWS / 8, 256>>>(x);
    center_kernel<<<MROWS, 256>>>();
    dim3 grid(NROWS / GBM, MROWS / GBN, KSPLIT);   // (24, 3, 4)
    mma_kernel<<<grid, 128>>>();
    reduce_kernel<<<NROWS / 8, 192>>>();
    finalize_kernel<<<1, 1>>>((float*)d_out);
}